// round 7
// baseline (speedup 1.0000x reference)
#include <cuda_runtime.h>
#include <cuda_fp16.h>
#include <cstdint>
#include <cstddef>

// CapsuleLayer fused: u_hat GEMM (fp16x3, mma.sync m16n8k16, SMEM-staged W,
// 4-c pipeline stages, hi/lo packed rows) + dynamic routing.
// One CTA per r, 512 threads. B=64, C=32, R=1152, IN=128, OUT=16, ITERS=3.

#define B_      64
#define C_      32
#define R_      1152
#define IN_     128
#define OUT_    16
#define STRIDE  516                       // C_*OUT_ + 4 pad floats (u_hat rows)
#define UH_BYTES (B_ * STRIDE * 4)        // 132096
#define ROWB    80                        // W smem row: 32B hi + 32B lo + 16B pad (16-aligned)
#define WTILE_B (IN_ * ROWB)              // one c tile (hi+lo): 128*80 = 10240 B
#define SMEM_BYTES (UH_BYTES + 2 * 4 * WTILE_B)   // 2 bufs x 4 c = +81920 -> 214016
#define NTHREADS 512

__device__ __forceinline__ unsigned h2bits(half2 h) {
    return *reinterpret_cast<unsigned*>(&h);
}
// v = hi + lo with hi,lo fp16 (packed pairs); ~22 effective bits
__device__ __forceinline__ void split2(float vx, float vy, unsigned& h, unsigned& l) {
    half2 hh = __floats2half2_rn(vx, vy);
    float2 hf = __half22float2(hh);
    half2 ll = __floats2half2_rn(vx - hf.x, vy - hf.y);
    h = h2bits(hh);
    l = h2bits(ll);
}

__device__ __forceinline__ void mma16(float& d0, float& d1, float& d2, float& d3,
                                      unsigned a0, unsigned a1, unsigned a2, unsigned a3,
                                      unsigned b0, unsigned b1) {
    asm volatile(
        "mma.sync.aligned.m16n8k16.row.col.f32.f16.f16.f32 "
        "{%0,%1,%2,%3}, {%4,%5,%6,%7}, {%8,%9}, {%0,%1,%2,%3};"
        : "+f"(d0), "+f"(d1), "+f"(d2), "+f"(d3)
        : "r"(a0), "r"(a1), "r"(a2), "r"(a3), "r"(b0), "r"(b1));
}

__device__ __forceinline__ void ldsm4t(unsigned& r0, unsigned& r1, unsigned& r2, unsigned& r3,
                                       unsigned addr) {
    asm volatile("ldmatrix.sync.aligned.m8n8.x4.trans.shared.b16 {%0,%1,%2,%3}, [%4];"
                 : "=r"(r0), "=r"(r1), "=r"(r2), "=r"(r3) : "r"(addr));
}

extern "C" __global__ void __launch_bounds__(NTHREADS, 1)
caps_fused_kernel(const float* __restrict__ X,      // (B, IN)  fp32
                  const float* __restrict__ W,      // (C, R, IN, OUT) fp32
                  float* __restrict__ out)          // (B, R, OUT) fp32
{
    extern __shared__ float uh_s[];                 // u_hat[b][c*16+o], stride 516
    char* wbuf = reinterpret_cast<char*>(uh_s) + UH_BYTES;

    const int r     = blockIdx.x;
    const int tid   = threadIdx.x;
    const int warp  = tid >> 5;    // 0..15
    const int lane  = tid & 31;
    const int group = lane >> 2;   // 0..7
    const int tig   = lane & 3;    // 0..3

    // ===== Phase 1: u_hat = x @ W[:, r] (fp16x3), 4 c-tiles per stage =====
    // Warp tiling: p = warp&3 -> b-block of 16 (2 mma n-tiles), g = warp>>2 -> c
    // among the 4 staged (c = 4*pi + g). Only 4 warps share each W tile's LDSM.
    const int p = warp & 3;        // 0..3
    const int g = warp >> 2;       // 0..3

    // B operand (x) fragments, fp16 hi/lo, two n-tiles (b = 16p.. / 16p+8..).
    unsigned xh0[16], xl0[16], xh1[16], xl1[16];
    {
        const float2* xr0 = reinterpret_cast<const float2*>(X) + (size_t)(16 * p + group) * (IN_ / 2);
        const float2* xr1 = reinterpret_cast<const float2*>(X) + (size_t)(16 * p + 8 + group) * (IN_ / 2);
#pragma unroll
        for (int kc = 0; kc < 8; ++kc) {
            float2 v;
            v = __ldg(xr0 + 8 * kc + tig);
            split2(v.x, v.y, xh0[2 * kc], xl0[2 * kc]);
            v = __ldg(xr0 + 8 * kc + tig + 4);
            split2(v.x, v.y, xh0[2 * kc + 1], xl0[2 * kc + 1]);
            v = __ldg(xr1 + 8 * kc + tig);
            split2(v.x, v.y, xh1[2 * kc], xl1[2 * kc]);
            v = __ldg(xr1 + 8 * kc + tig + 4);
            split2(v.x, v.y, xh1[2 * kc + 1], xl1[2 * kc + 1]);
        }
    }

    // Staging role: per stage this thread stores one float4 per c:
    //   i = tid/4 (0..127), o4 = (tid%4)*4.
    const int st_i  = tid >> 2;
    const int st_o4 = (tid & 3) << 2;
    const float* Wr = W + (size_t)r * (IN_ * OUT_);
    const size_t cstride = (size_t)R_ * (IN_ * OUT_);

    // ldmatrix source (within a c tile; hi at row+0, lo at row+32):
    //   mat0: lanes 0-7   -> rows i=0..7,  col 0   (a0: o0-7,  k0-7)
    //   mat1: lanes 8-15  -> rows i=0..7,  col 8   (a1: o8-15, k0-7)
    //   mat2: lanes 16-23 -> rows i=8..15, col 0   (a2: o0-7,  k8-15)
    //   mat3: lanes 24-31 -> rows i=8..15, col 8   (a3: o8-15, k8-15)
    const int lm_i = (lane & 7) + ((lane >> 4) << 3);
    const int lm_byte = lm_i * ROWB + ((lane & 8) ? 16 : 0);     // multiples of 16
    const unsigned wbuf_s = (unsigned)__cvta_generic_to_shared(wbuf);

    // prefetch stage 0 (c = 0..3)
    float4 vA0 = __ldg(reinterpret_cast<const float4*>(Wr + 0 * cstride + st_i * OUT_ + st_o4));
    float4 vA1 = __ldg(reinterpret_cast<const float4*>(Wr + 1 * cstride + st_i * OUT_ + st_o4));
    float4 vA2 = __ldg(reinterpret_cast<const float4*>(Wr + 2 * cstride + st_i * OUT_ + st_o4));
    float4 vA3 = __ldg(reinterpret_cast<const float4*>(Wr + 3 * cstride + st_i * OUT_ + st_o4));

#pragma unroll 1
    for (int pi = 0; pi < 8; ++pi) {
        const int buf = pi & 1;
        // ---- split + store the 4 staged c's into wbuf[buf] ----
        {
            const int boff = st_i * ROWB + st_o4 * 2;            // hi at +0, lo at +32
            char* base = wbuf + (size_t)(buf * 4) * WTILE_B + boff;
            unsigned h01, l01, h23, l23;
            split2(vA0.x, vA0.y, h01, l01);
            split2(vA0.z, vA0.w, h23, l23);
            *reinterpret_cast<uint2*>(base + 0 * WTILE_B)      = make_uint2(h01, h23);
            *reinterpret_cast<uint2*>(base + 0 * WTILE_B + 32) = make_uint2(l01, l23);
            split2(vA1.x, vA1.y, h01, l01);
            split2(vA1.z, vA1.w, h23, l23);
            *reinterpret_cast<uint2*>(base + 1 * WTILE_B)      = make_uint2(h01, h23);
            *reinterpret_cast<uint2*>(base + 1 * WTILE_B + 32) = make_uint2(l01, l23);
            split2(vA2.x, vA2.y, h01, l01);
            split2(vA2.z, vA2.w, h23, l23);
            *reinterpret_cast<uint2*>(base + 2 * WTILE_B)      = make_uint2(h01, h23);
            *reinterpret_cast<uint2*>(base + 2 * WTILE_B + 32) = make_uint2(l01, l23);
            split2(vA3.x, vA3.y, h01, l01);
            split2(vA3.z, vA3.w, h23, l23);
            *reinterpret_cast<uint2*>(base + 3 * WTILE_B)      = make_uint2(h01, h23);
            *reinterpret_cast<uint2*>(base + 3 * WTILE_B + 32) = make_uint2(l01, l23);
        }
        // ---- prefetch next stage ----
        if (pi < 7) {
            const float* Wn = Wr + (size_t)(4 * pi + 4) * cstride + st_i * OUT_ + st_o4;
            vA0 = __ldg(reinterpret_cast<const float4*>(Wn));
            vA1 = __ldg(reinterpret_cast<const float4*>(Wn + cstride));
            vA2 = __ldg(reinterpret_cast<const float4*>(Wn + 2 * cstride));
            vA3 = __ldg(reinterpret_cast<const float4*>(Wn + 3 * cstride));
        }
        __syncthreads();

        // ---- MMA for c = 4*pi + g ----
        const unsigned hbase = wbuf_s + (unsigned)(buf * 4 + g) * WTILE_B + lm_byte;

        float d0 = 0.f, d1 = 0.f, d2 = 0.f, d3 = 0.f;   // n-tile 0 (b = 16p+..)
        float e0 = 0.f, e1 = 0.f, e2 = 0.f, e3 = 0.f;   // n-tile 1 (b = 16p+8+..)
#pragma unroll
        for (int kc = 0; kc < 8; ++kc) {
            unsigned ah0, ah1, ah2, ah3, al0, al1, al2, al3;
            const unsigned ka = hbase + (unsigned)(16 * kc) * ROWB;
            ldsm4t(ah0, ah1, ah2, ah3, ka);
            ldsm4t(al0, al1, al2, al3, ka + 32);
            // 3-term fp16 split, interleaved over the two independent chains
            mma16(d0, d1, d2, d3, ah0, ah1, ah2, ah3, xh0[2 * kc], xh0[2 * kc + 1]);
            mma16(e0, e1, e2, e3, ah0, ah1, ah2, ah3, xh1[2 * kc], xh1[2 * kc + 1]);
            mma16(d0, d1, d2, d3, al0, al1, al2, al3, xh0[2 * kc], xh0[2 * kc + 1]);
            mma16(e0, e1, e2, e3, al0, al1, al2, al3, xh1[2 * kc], xh1[2 * kc + 1]);
            mma16(d0, d1, d2, d3, ah0, ah1, ah2, ah3, xl0[2 * kc], xl0[2 * kc + 1]);
            mma16(e0, e1, e2, e3, ah0, ah1, ah2, ah3, xl1[2 * kc], xl1[2 * kc + 1]);
        }

        // D frags -> uh_s: tile0 d: (o=group, b=16p+2tig | +1), (o=group+8, same b)
        //                  tile1 e: same with b += 8
        {
            const int c  = 4 * pi + g;
            const int b0 = 16 * p + 2 * tig;
            float* u0 = uh_s + (size_t)b0 * STRIDE + c * OUT_ + group;
            u0[0]          = d0;
            u0[STRIDE]     = d1;
            u0[8]          = d2;
            u0[STRIDE + 8] = d3;
            float* u1 = uh_s + (size_t)(b0 + 8) * STRIDE + c * OUT_ + group;
            u1[0]          = e0;
            u1[STRIDE]     = e1;
            u1[8]          = e2;
            u1[STRIDE + 8] = e3;
        }
        __syncthreads();   // wbuf[buf] fully consumed before refill at pi+2
    }

    // ========== Phase 2: dynamic routing (3 iters), warp = 4 b's ==========
    const unsigned FULL = 0xffffffffu;
#pragma unroll 1
    for (int bb = 0; bb < 4; ++bb) {
        const int b = warp * 4 + bb;
        const float* row = uh_s + (size_t)b * STRIDE;

        float uh[16];   // lane = c view of u_hat[b][lane][:]
#pragma unroll
        for (int q4 = 0; q4 < 4; ++q4) {
            float4 v4 = *reinterpret_cast<const float4*>(row + lane * OUT_ + 4 * q4);
            uh[4 * q4 + 0] = v4.x;
            uh[4 * q4 + 1] = v4.y;
            uh[4 * q4 + 2] = v4.z;
            uh[4 * q4 + 3] = v4.w;
        }

        float blog = 0.0f;
        const int o = lane & 15;

#pragma unroll 1
        for (int it = 0; it < 3; ++it) {
            float m = blog;
#pragma unroll
            for (int s = 16; s > 0; s >>= 1)
                m = fmaxf(m, __shfl_xor_sync(FULL, m, s));
            float e = __expf(blog - m);
            float Z = e;
#pragma unroll
            for (int s = 16; s > 0; s >>= 1)
                Z += __shfl_xor_sync(FULL, Z, s);
            const float ccf = e / Z;

            float sv = 0.0f;
#pragma unroll
            for (int c2 = 0; c2 < 32; ++c2)
                sv = fmaf(__shfl_sync(FULL, ccf, c2), row[c2 * OUT_ + o], sv);

            float n2 = sv * sv;
#pragma unroll
            for (int s = 8; s > 0; s >>= 1)
                n2 += __shfl_xor_sync(FULL, n2, s);
            const float nrm = sqrtf(n2);
            const float vo  = (n2 / (1.0f + n2)) * (sv / nrm);

            if (it < 2) {
                float acc = 0.0f;
#pragma unroll
                for (int o2 = 0; o2 < 16; ++o2)
                    acc = fmaf(uh[o2], __shfl_sync(FULL, vo, o2), acc);
                blog += acc;
            } else if (lane < 16) {
                out[((size_t)b * R_ + r) * OUT_ + o] = vo;
            }
        }
    }
}

extern "C" void kernel_launch(void* const* d_in, const int* in_sizes, int n_in,
                              void* d_out, int out_size) {
    (void)n_in; (void)out_size;
    const float* a = (const float*)d_in[0];
    const float* b = (const float*)d_in[1];
    const float* X = a;
    const float* W = b;
    if (in_sizes[0] != B_ * IN_) { X = b; W = a; }

    cudaFuncSetAttribute(caps_fused_kernel,
                         cudaFuncAttributeMaxDynamicSharedMemorySize, SMEM_BYTES);
    caps_fused_kernel<<<R_, NTHREADS, SMEM_BYTES>>>(X, W, (float*)d_out);
}

// round 8
// speedup vs baseline: 1.3049x; 1.3049x over previous
#include <cuda_runtime.h>
#include <cuda_fp16.h>
#include <cstdint>
#include <cstddef>

// CapsuleLayer, two-kernel version.
//  K1: u_hat = x @ W  (fp16x3, mma.sync m16n8k16, SMEM-staged W, persistent CTAs)
//      -> g_uhat scratch, layout (b, r, c, o)
//  K2: dynamic routing, warp per (b,r), register-resident, shfl-only.
// B=64, C=32, R=1152, IN=128, OUT=16, ITERS=3.

#define B_      64
#define C_      32
#define R_      1152
#define IN_     128
#define OUT_    16
#define ROWB    80                         // W smem row: 32B hi + 32B lo + 16B pad
#define WTILE_B (IN_ * ROWB)               // one r tile (hi+lo): 10240 B
#define SMEM1_BYTES (2 * 4 * WTILE_B)      // 2 bufs x 4 r-tiles = 81920
#define GEMM_CTAS   144                    // persistent; 16 tasks each (144*16 = 2304)
#define BSTR  ((size_t)R_ * C_ * OUT_)     // b-stride in g_uhat = 589824

__device__ float g_uhat[(size_t)B_ * R_ * C_ * OUT_];   // 151 MB scratch

__device__ __forceinline__ unsigned h2bits(half2 h) {
    return *reinterpret_cast<unsigned*>(&h);
}
// v = hi + lo with hi,lo fp16 (packed pairs); ~22 effective bits
__device__ __forceinline__ void split2(float vx, float vy, unsigned& h, unsigned& l) {
    half2 hh = __floats2half2_rn(vx, vy);
    float2 hf = __half22float2(hh);
    half2 ll = __floats2half2_rn(vx - hf.x, vy - hf.y);
    h = h2bits(hh);
    l = h2bits(ll);
}

__device__ __forceinline__ void mma16(float& d0, float& d1, float& d2, float& d3,
                                      unsigned a0, unsigned a1, unsigned a2, unsigned a3,
                                      unsigned b0, unsigned b1) {
    asm volatile(
        "mma.sync.aligned.m16n8k16.row.col.f32.f16.f16.f32 "
        "{%0,%1,%2,%3}, {%4,%5,%6,%7}, {%8,%9}, {%0,%1,%2,%3};"
        : "+f"(d0), "+f"(d1), "+f"(d2), "+f"(d3)
        : "r"(a0), "r"(a1), "r"(a2), "r"(a3), "r"(b0), "r"(b1));
}

__device__ __forceinline__ void ldsm4t(unsigned& r0, unsigned& r1, unsigned& r2, unsigned& r3,
                                       unsigned addr) {
    asm volatile("ldmatrix.sync.aligned.m8n8.x4.trans.shared.b16 {%0,%1,%2,%3}, [%4];"
                 : "=r"(r0), "=r"(r1), "=r"(r2), "=r"(r3) : "r"(addr));
}

// ===================== Kernel 1: GEMM -> g_uhat =====================
// Task t (0..2303): c = t/72, rb = t%72 -> r block rb*16..rb*16+15.
// CTA does tasks bid*16 .. bid*16+15 (64 stages of 4 r-tiles).
// Warp tiling: p = warp&3 -> b-tile of 16 (2 mma n-tiles); g = warp>>2 -> r of stage.

extern "C" __global__ void __launch_bounds__(512, 1)
caps_gemm_kernel(const float* __restrict__ X,      // (B, IN)
                 const float* __restrict__ W)      // (C, R, IN, OUT)
{
    extern __shared__ char wbuf[];                  // 2 bufs x 4 tiles x WTILE_B

    const int bid   = blockIdx.x;
    const int tid   = threadIdx.x;
    const int warp  = tid >> 5;
    const int lane  = tid & 31;
    const int group = lane >> 2;   // 0..7
    const int tig   = lane & 3;    // 0..3
    const int p = warp & 3;
    const int g = warp >> 2;

    // x fragments (fp16 hi/lo), two n-tiles: b = 16p+group / 16p+8+group. Loaded ONCE.
    unsigned xh0[16], xl0[16], xh1[16], xl1[16];
    {
        const float2* xr0 = reinterpret_cast<const float2*>(X) + (size_t)(16 * p + group) * (IN_ / 2);
        const float2* xr1 = reinterpret_cast<const float2*>(X) + (size_t)(16 * p + 8 + group) * (IN_ / 2);
#pragma unroll
        for (int kc = 0; kc < 8; ++kc) {
            float2 v;
            v = __ldg(xr0 + 8 * kc + tig);
            split2(v.x, v.y, xh0[2 * kc], xl0[2 * kc]);
            v = __ldg(xr0 + 8 * kc + tig + 4);
            split2(v.x, v.y, xh0[2 * kc + 1], xl0[2 * kc + 1]);
            v = __ldg(xr1 + 8 * kc + tig);
            split2(v.x, v.y, xh1[2 * kc], xl1[2 * kc]);
            v = __ldg(xr1 + 8 * kc + tig + 4);
            split2(v.x, v.y, xh1[2 * kc + 1], xl1[2 * kc + 1]);
        }
    }

    const int st_i  = tid >> 2;            // 0..127
    const int st_o4 = (tid & 3) << 2;      // 0,4,8,12

    const int lm_i = (lane & 7) + ((lane >> 4) << 3);
    const int lm_byte = lm_i * ROWB + ((lane & 8) ? 16 : 0);
    const unsigned wbuf_s = (unsigned)__cvta_generic_to_shared(wbuf);

    // stage -> W base of its 4 contiguous r tiles
    auto stage_base = [&](int s) -> const float* {
        int task = bid * 16 + (s >> 2);
        int c  = task / 72;
        int rb = task - c * 72;
        return W + ((size_t)c * R_ + rb * 16 + (s & 3) * 4) * (IN_ * OUT_);
    };

    // prefetch stage 0
    const float* Ws = stage_base(0);
    float4 vA0 = __ldg(reinterpret_cast<const float4*>(Ws + 0 * 2048 + st_i * OUT_ + st_o4));
    float4 vA1 = __ldg(reinterpret_cast<const float4*>(Ws + 1 * 2048 + st_i * OUT_ + st_o4));
    float4 vA2 = __ldg(reinterpret_cast<const float4*>(Ws + 2 * 2048 + st_i * OUT_ + st_o4));
    float4 vA3 = __ldg(reinterpret_cast<const float4*>(Ws + 3 * 2048 + st_i * OUT_ + st_o4));

#pragma unroll 1
    for (int s = 0; s < 64; ++s) {
        const int buf = s & 1;
        // ---- split + store the 4 staged r tiles ----
        {
            const int boff = st_i * ROWB + st_o4 * 2;            // hi at +0, lo at +32
            char* base = wbuf + (size_t)(buf * 4) * WTILE_B + boff;
            unsigned h01, l01, h23, l23;
            split2(vA0.x, vA0.y, h01, l01);
            split2(vA0.z, vA0.w, h23, l23);
            *reinterpret_cast<uint2*>(base + 0 * WTILE_B)      = make_uint2(h01, h23);
            *reinterpret_cast<uint2*>(base + 0 * WTILE_B + 32) = make_uint2(l01, l23);
            split2(vA1.x, vA1.y, h01, l01);
            split2(vA1.z, vA1.w, h23, l23);
            *reinterpret_cast<uint2*>(base + 1 * WTILE_B)      = make_uint2(h01, h23);
            *reinterpret_cast<uint2*>(base + 1 * WTILE_B + 32) = make_uint2(l01, l23);
            split2(vA2.x, vA2.y, h01, l01);
            split2(vA2.z, vA2.w, h23, l23);
            *reinterpret_cast<uint2*>(base + 2 * WTILE_B)      = make_uint2(h01, h23);
            *reinterpret_cast<uint2*>(base + 2 * WTILE_B + 32) = make_uint2(l01, l23);
            split2(vA3.x, vA3.y, h01, l01);
            split2(vA3.z, vA3.w, h23, l23);
            *reinterpret_cast<uint2*>(base + 3 * WTILE_B)      = make_uint2(h01, h23);
            *reinterpret_cast<uint2*>(base + 3 * WTILE_B + 32) = make_uint2(l01, l23);
        }
        // ---- prefetch next stage ----
        if (s < 63) {
            const float* Wn = stage_base(s + 1) + st_i * OUT_ + st_o4;
            vA0 = __ldg(reinterpret_cast<const float4*>(Wn));
            vA1 = __ldg(reinterpret_cast<const float4*>(Wn + 2048));
            vA2 = __ldg(reinterpret_cast<const float4*>(Wn + 4096));
            vA3 = __ldg(reinterpret_cast<const float4*>(Wn + 6144));
        }
        __syncthreads();

        // ---- MMA on r-tile g of this stage ----
        const unsigned hbase = wbuf_s + (unsigned)(buf * 4 + g) * WTILE_B + lm_byte;

        float d0 = 0.f, d1 = 0.f, d2 = 0.f, d3 = 0.f;   // n-tile 0 (b = 16p+..)
        float e0 = 0.f, e1 = 0.f, e2 = 0.f, e3 = 0.f;   // n-tile 1 (b = 16p+8+..)
#pragma unroll
        for (int kc = 0; kc < 8; ++kc) {
            unsigned ah0, ah1, ah2, ah3, al0, al1, al2, al3;
            const unsigned ka = hbase + (unsigned)(16 * kc) * ROWB;
            ldsm4t(ah0, ah1, ah2, ah3, ka);
            ldsm4t(al0, al1, al2, al3, ka + 32);
            mma16(d0, d1, d2, d3, ah0, ah1, ah2, ah3, xh0[2 * kc], xh0[2 * kc + 1]);
            mma16(e0, e1, e2, e3, ah0, ah1, ah2, ah3, xh1[2 * kc], xh1[2 * kc + 1]);
            mma16(d0, d1, d2, d3, al0, al1, al2, al3, xh0[2 * kc], xh0[2 * kc + 1]);
            mma16(e0, e1, e2, e3, al0, al1, al2, al3, xh1[2 * kc], xh1[2 * kc + 1]);
            mma16(d0, d1, d2, d3, ah0, ah1, ah2, ah3, xl0[2 * kc], xl0[2 * kc + 1]);
            mma16(e0, e1, e2, e3, ah0, ah1, ah2, ah3, xl1[2 * kc], xl1[2 * kc + 1]);
        }

        // ---- store D frags to g_uhat (b, r, c, o) ----
        // d0=(o=group, b=b0), d1=(group, b0+1), d2=(group+8, b0), d3=(group+8, b0+1)
        // e*: same with b += 8.  Each STG: 8 lanes x 4B contiguous = full 32B sectors.
        {
            int task = bid * 16 + (s >> 2);
            int c  = task / 72;
            int rb = task - c * 72;
            int r  = rb * 16 + (s & 3) * 4 + g;
            const size_t rc = ((size_t)r * C_ + c) * OUT_;
            const int b0 = 16 * p + 2 * tig;
            float* u0 = g_uhat + (size_t)b0 * BSTR + rc + group;
            u0[0]        = d0;
            u0[BSTR]     = d1;
            u0[8]        = d2;
            u0[BSTR + 8] = d3;
            float* u1 = u0 + 8 * BSTR;
            u1[0]        = e0;
            u1[BSTR]     = e1;
            u1[8]        = e2;
            u1[BSTR + 8] = e3;
        }
        __syncthreads();   // wbuf[buf] fully consumed before refill at s+2
    }
}

// ===================== Kernel 2: dynamic routing =====================
// Warp per (b,r). lane = c. u_hat row (32c x 16o) in registers. No smem/LDS.

extern "C" __global__ void __launch_bounds__(256)
caps_route_kernel(float* __restrict__ out)          // (B, R, OUT)
{
    const unsigned FULL = 0xffffffffu;
    const int lane = threadIdx.x & 31;
    const int pair = blockIdx.x * 8 + (threadIdx.x >> 5);   // 0..73727
    const int b = pair / R_;
    const int r = pair - b * R_;

    // load u_hat[b, r, c=lane, 0..15]  (warp reads 2KB contiguous)
    float uh[16];
    {
        const float4* up = reinterpret_cast<const float4*>(
            g_uhat + ((size_t)b * R_ + r) * (C_ * OUT_) + lane * OUT_);
        float4 v;
        v = __ldg(up + 0); uh[0] = v.x; uh[1] = v.y; uh[2] = v.z; uh[3] = v.w;
        v = __ldg(up + 1); uh[4] = v.x; uh[5] = v.y; uh[6] = v.z; uh[7] = v.w;
        v = __ldg(up + 2); uh[8] = v.x; uh[9] = v.y; uh[10] = v.z; uh[11] = v.w;
        v = __ldg(up + 3); uh[12] = v.x; uh[13] = v.y; uh[14] = v.z; uh[15] = v.w;
    }

    float blog = 0.0f;                     // routing logit b[b, c=lane, r]

#pragma unroll 1
    for (int it = 0; it < 3; ++it) {
        // softmax over c (32 lanes)
        float m = blog;
#pragma unroll
        for (int s = 16; s > 0; s >>= 1)
            m = fmaxf(m, __shfl_xor_sync(FULL, m, s));
        float e = __expf(blog - m);
        float Z = e;
#pragma unroll
        for (int s = 16; s > 0; s >>= 1)
            Z += __shfl_xor_sync(FULL, Z, s);
        const float cc = e / Z;

        // s[o] = sum_c cc*uh[c][o] via reduce-scatter; lane ends with s[lane&15]
        float q[16];
#pragma unroll
        for (int o = 0; o < 16; ++o) q[o] = cc * uh[o];
#pragma unroll
        for (int i = 0; i < 16; ++i) q[i] += __shfl_xor_sync(FULL, q[i], 16);
        float q8[8];
        {
            const bool up8 = (lane & 8) != 0;
#pragma unroll
            for (int i = 0; i < 8; ++i) {
                float snd = up8 ? q[i]     : q[i + 8];
                float kp  = up8 ? q[i + 8] : q[i];
                q8[i] = kp + __shfl_xor_sync(FULL, snd, 8);
            }
        }
        float q4[4];
        {
            const bool up4 = (lane & 4) != 0;
#pragma unroll
            for (int i = 0; i < 4; ++i) {
                float snd = up4 ? q8[i]     : q8[i + 4];
                float kp  = up4 ? q8[i + 4] : q8[i];
                q4[i] = kp + __shfl_xor_sync(FULL, snd, 4);
            }
        }
        float q2[2];
        {
            const bool up2 = (lane & 2) != 0;
#pragma unroll
            for (int i = 0; i < 2; ++i) {
                float snd = up2 ? q4[i]     : q4[i + 2];
                float kp  = up2 ? q4[i + 2] : q4[i];
                q2[i] = kp + __shfl_xor_sync(FULL, snd, 2);
            }
        }
        float sv;
        {
            const bool up1 = (lane & 1) != 0;
            float snd = up1 ? q2[0] : q2[1];
            float kp  = up1 ? q2[1] : q2[0];
            sv = kp + __shfl_xor_sync(FULL, snd, 1);
        }
        // lane holds s[o], o = lane&15 (duplicated in both halves)

        // squash
        float n2 = sv * sv;
#pragma unroll
        for (int s = 8; s > 0; s >>= 1)
            n2 += __shfl_xor_sync(FULL, n2, s);
        const float nrm = sqrtf(n2);
        const float vo  = (n2 / (1.0f + n2)) * (sv / nrm);

        if (it < 2) {
            // b[c] += sum_o uh[c][o]*v[o]  (v broadcast from lanes 0..15)
            float acc = 0.0f;
#pragma unroll
            for (int o2 = 0; o2 < 16; ++o2)
                acc = fmaf(uh[o2], __shfl_sync(FULL, vo, o2), acc);
            blog += acc;
        } else if (lane < 16) {
            out[((size_t)b * R_ + r) * OUT_ + lane] = vo;
        }
    }
}

extern "C" void kernel_launch(void* const* d_in, const int* in_sizes, int n_in,
                              void* d_out, int out_size) {
    (void)n_in; (void)out_size;
    const float* a = (const float*)d_in[0];
    const float* b = (const float*)d_in[1];
    const float* X = a;
    const float* W = b;
    if (in_sizes[0] != B_ * IN_) { X = b; W = a; }

    cudaFuncSetAttribute(caps_gemm_kernel,
                         cudaFuncAttributeMaxDynamicSharedMemorySize, SMEM1_BYTES);
    caps_gemm_kernel<<<GEMM_CTAS, 512, SMEM1_BYTES>>>(X, W);
    caps_route_kernel<<<(B_ * R_) / 8, 256>>>((float*)d_out);
}

// round 10
// speedup vs baseline: 1.4360x; 1.1004x over previous
#include <cuda_runtime.h>
#include <cuda_fp16.h>
#include <cstdint>
#include <cstddef>

// CapsuleLayer, two-kernel version.
//  K1: u_hat = x @ W  (fp16x3, mma.sync m16n8k16, SMEM-staged W, persistent CTAs,
//      256 thr / 2 CTAs per SM) -> g_uhat scratch, layout (b, r, c, o)
//  K2: dynamic routing, warp per (b,r), register-resident, reduced-shfl.
// B=64, C=32, R=1152, IN=128, OUT=16, ITERS=3.

#define B_      64
#define C_      32
#define R_      1152
#define IN_     128
#define OUT_    16
#define ROWB    80                         // W smem row: 32B hi + 32B lo + 16B pad
#define WTILE_B (IN_ * ROWB)               // one r tile (hi+lo): 10240 B
#define SMEM1_BYTES (2 * 2 * WTILE_B)      // 2 bufs x 2 r-tiles = 40960
#define GEMM_CTAS   288                    // persistent; 8 tasks each (288*8 = 2304)
#define NT1   256
#define BSTR  ((size_t)R_ * C_ * OUT_)     // b-stride in g_uhat = 589824

__device__ float g_uhat[(size_t)B_ * R_ * C_ * OUT_];   // 151 MB scratch

__device__ __forceinline__ unsigned h2bits(half2 h) {
    return *reinterpret_cast<unsigned*>(&h);
}
// v = hi + lo with hi,lo fp16 (packed pairs); ~22 effective bits
__device__ __forceinline__ void split2(float vx, float vy, unsigned& h, unsigned& l) {
    half2 hh = __floats2half2_rn(vx, vy);
    float2 hf = __half22float2(hh);
    half2 ll = __floats2half2_rn(vx - hf.x, vy - hf.y);
    h = h2bits(hh);
    l = h2bits(ll);
}

__device__ __forceinline__ void mma16(float& d0, float& d1, float& d2, float& d3,
                                      unsigned a0, unsigned a1, unsigned a2, unsigned a3,
                                      unsigned b0, unsigned b1) {
    asm volatile(
        "mma.sync.aligned.m16n8k16.row.col.f32.f16.f16.f32 "
        "{%0,%1,%2,%3}, {%4,%5,%6,%7}, {%8,%9}, {%0,%1,%2,%3};"
        : "+f"(d0), "+f"(d1), "+f"(d2), "+f"(d3)
        : "r"(a0), "r"(a1), "r"(a2), "r"(a3), "r"(b0), "r"(b1));
}

__device__ __forceinline__ void ldsm4t(unsigned& r0, unsigned& r1, unsigned& r2, unsigned& r3,
                                       unsigned addr) {
    asm volatile("ldmatrix.sync.aligned.m8n8.x4.trans.shared.b16 {%0,%1,%2,%3}, [%4];"
                 : "=r"(r0), "=r"(r1), "=r"(r2), "=r"(r3) : "r"(addr));
}

// ===================== Kernel 1: GEMM -> g_uhat =====================
// Task t (0..2303): c = t/72, rb = t%72 -> r block rb*16..rb*16+15.
// CTA does tasks bid*8 .. bid*8+7; 64 stages of 2 r-tiles (sub = s&7, r = rb*16+2*sub+g).
// Warps: p = warp&3 -> b-tile of 16 (2 mma n-tiles); g = warp>>2 (0/1) -> tile of stage.

extern "C" __global__ void __launch_bounds__(NT1, 2)
caps_gemm_kernel(const float* __restrict__ X,      // (B, IN)
                 const float* __restrict__ W)      // (C, R, IN, OUT)
{
    extern __shared__ char wbuf[];                  // 2 bufs x 2 tiles x WTILE_B

    const int bid   = blockIdx.x;
    const int tid   = threadIdx.x;
    const int warp  = tid >> 5;    // 0..7
    const int lane  = tid & 31;
    const int group = lane >> 2;   // 0..7
    const int tig   = lane & 3;    // 0..3
    const int p = warp & 3;
    const int g = warp >> 2;       // 0/1

    // x fragments (fp16 hi/lo), two n-tiles: b = 16p+group / 16p+8+group. Loaded ONCE.
    unsigned xh0[16], xl0[16], xh1[16], xl1[16];
    {
        const float2* xr0 = reinterpret_cast<const float2*>(X) + (size_t)(16 * p + group) * (IN_ / 2);
        const float2* xr1 = reinterpret_cast<const float2*>(X) + (size_t)(16 * p + 8 + group) * (IN_ / 2);
#pragma unroll
        for (int kc = 0; kc < 8; ++kc) {
            float2 v;
            v = __ldg(xr0 + 8 * kc + tig);
            split2(v.x, v.y, xh0[2 * kc], xl0[2 * kc]);
            v = __ldg(xr0 + 8 * kc + tig + 4);
            split2(v.x, v.y, xh0[2 * kc + 1], xl0[2 * kc + 1]);
            v = __ldg(xr1 + 8 * kc + tig);
            split2(v.x, v.y, xh1[2 * kc], xl1[2 * kc]);
            v = __ldg(xr1 + 8 * kc + tig + 4);
            split2(v.x, v.y, xh1[2 * kc + 1], xl1[2 * kc + 1]);
        }
    }

    // Staging role: thread t handles row i = t>>1, float4 pair at o4 = (t&1)*8, +4.
    const int st_i  = tid >> 1;            // 0..127
    const int st_h  = tid & 1;             // 0/1
    const int st_off = st_i * OUT_ + st_h * 8;       // float offset in tile

    const int lm_i = (lane & 7) + ((lane >> 4) << 3);
    const int lm_byte = lm_i * ROWB + ((lane & 8) ? 16 : 0);
    const unsigned wbuf_s = (unsigned)__cvta_generic_to_shared(wbuf);

    // stage -> W base of its 2 r tiles
    auto stage_base = [&](int s) -> const float* {
        int task = bid * 8 + (s >> 3);
        int c  = task / 72;
        int rb = task - c * 72;
        return W + ((size_t)c * R_ + rb * 16 + (s & 7) * 2) * (IN_ * OUT_);
    };

    // prefetch stage 0: 2 float4 per tile, 2 tiles
    const float* Ws = stage_base(0);
    float4 vA0 = __ldg(reinterpret_cast<const float4*>(Ws + st_off));
    float4 vA1 = __ldg(reinterpret_cast<const float4*>(Ws + st_off + 4));
    float4 vB0 = __ldg(reinterpret_cast<const float4*>(Ws + 2048 + st_off));
    float4 vB1 = __ldg(reinterpret_cast<const float4*>(Ws + 2048 + st_off + 4));

#pragma unroll 1
    for (int s = 0; s < 64; ++s) {
        const int buf = s & 1;
        // ---- split + store the 2 staged r tiles ----
        {
            const int b0 = st_i * ROWB + (st_h * 8) * 2;         // hi at +0, lo at +32
            char* baseA = wbuf + (size_t)(buf * 2 + 0) * WTILE_B + b0;
            char* baseB = wbuf + (size_t)(buf * 2 + 1) * WTILE_B + b0;
            unsigned h01, l01, h23, l23;
            split2(vA0.x, vA0.y, h01, l01);
            split2(vA0.z, vA0.w, h23, l23);
            *reinterpret_cast<uint2*>(baseA)      = make_uint2(h01, h23);
            *reinterpret_cast<uint2*>(baseA + 32) = make_uint2(l01, l23);
            split2(vA1.x, vA1.y, h01, l01);
            split2(vA1.z, vA1.w, h23, l23);
            *reinterpret_cast<uint2*>(baseA + 8)      = make_uint2(h01, h23);
            *reinterpret_cast<uint2*>(baseA + 8 + 32) = make_uint2(l01, l23);
            split2(vB0.x, vB0.y, h01, l01);
            split2(vB0.z, vB0.w, h23, l23);
            *reinterpret_cast<uint2*>(baseB)      = make_uint2(h01, h23);
            *reinterpret_cast<uint2*>(baseB + 32) = make_uint2(l01, l23);
            split2(vB1.x, vB1.y, h01, l01);
            split2(vB1.z, vB1.w, h23, l23);
            *reinterpret_cast<uint2*>(baseB + 8)      = make_uint2(h01, h23);
            *reinterpret_cast<uint2*>(baseB + 8 + 32) = make_uint2(l01, l23);
        }
        // ---- prefetch next stage ----
        if (s < 63) {
            const float* Wn = stage_base(s + 1);
            vA0 = __ldg(reinterpret_cast<const float4*>(Wn + st_off));
            vA1 = __ldg(reinterpret_cast<const float4*>(Wn + st_off + 4));
            vB0 = __ldg(reinterpret_cast<const float4*>(Wn + 2048 + st_off));
            vB1 = __ldg(reinterpret_cast<const float4*>(Wn + 2048 + st_off + 4));
        }
        __syncthreads();

        // ---- MMA on tile g of this stage ----
        const unsigned hbase = wbuf_s + (unsigned)(buf * 2 + g) * WTILE_B + lm_byte;

        float d0 = 0.f, d1 = 0.f, d2 = 0.f, d3 = 0.f;   // n-tile 0 (b = 16p+..)
        float e0 = 0.f, e1 = 0.f, e2 = 0.f, e3 = 0.f;   // n-tile 1 (b = 16p+8+..)
#pragma unroll
        for (int kc = 0; kc < 8; ++kc) {
            unsigned ah0, ah1, ah2, ah3, al0, al1, al2, al3;
            const unsigned ka = hbase + (unsigned)(16 * kc) * ROWB;
            ldsm4t(ah0, ah1, ah2, ah3, ka);
            ldsm4t(al0, al1, al2, al3, ka + 32);
            mma16(d0, d1, d2, d3, ah0, ah1, ah2, ah3, xh0[2 * kc], xh0[2 * kc + 1]);
            mma16(e0, e1, e2, e3, ah0, ah1, ah2, ah3, xh1[2 * kc], xh1[2 * kc + 1]);
            mma16(d0, d1, d2, d3, al0, al1, al2, al3, xh0[2 * kc], xh0[2 * kc + 1]);
            mma16(e0, e1, e2, e3, al0, al1, al2, al3, xh1[2 * kc], xh1[2 * kc + 1]);
            mma16(d0, d1, d2, d3, ah0, ah1, ah2, ah3, xl0[2 * kc], xl0[2 * kc + 1]);
            mma16(e0, e1, e2, e3, ah0, ah1, ah2, ah3, xl1[2 * kc], xl1[2 * kc + 1]);
        }

        // ---- store D frags to g_uhat (b, r, c, o) ----
        {
            int task = bid * 8 + (s >> 3);
            int c  = task / 72;
            int rb = task - c * 72;
            int r  = rb * 16 + (s & 7) * 2 + g;
            const size_t rc = ((size_t)r * C_ + c) * OUT_;
            const int b0 = 16 * p + 2 * tig;
            float* u0 = g_uhat + (size_t)b0 * BSTR + rc + group;
            u0[0]        = d0;
            u0[BSTR]     = d1;
            u0[8]        = d2;
            u0[BSTR + 8] = d3;
            float* u1 = u0 + 8 * BSTR;
            u1[0]        = e0;
            u1[BSTR]     = e1;
            u1[8]        = e2;
            u1[BSTR + 8] = e3;
        }
        __syncthreads();   // wbuf[buf] fully consumed before refill at s+2
    }
}

// ===================== Kernel 2: dynamic routing =====================
// Warp per (b,r). lane = c. u_hat row (32c x 16o) in registers. Reduced shfl count:
// iter0 softmax skipped (uniform 1/32); 16-shfl reduce-scatter; 4-shfl n2.

extern "C" __global__ void __launch_bounds__(256)
caps_route_kernel(float* __restrict__ out)          // (B, R, OUT)
{
    const unsigned FULL = 0xffffffffu;
    const int lane = threadIdx.x & 31;
    const int pair = blockIdx.x * 8 + (threadIdx.x >> 5);   // 0..73727
    const int b = pair / R_;
    const int r = pair - b * R_;

    // load u_hat[b, r, c=lane, 0..15]  (warp reads 2KB contiguous)
    float uh[16];
    {
        const float4* up = reinterpret_cast<const float4*>(
            g_uhat + ((size_t)b * R_ + r) * (C_ * OUT_) + lane * OUT_);
        float4 v;
        v = __ldg(up + 0); uh[0] = v.x; uh[1] = v.y; uh[2] = v.z; uh[3] = v.w;
        v = __ldg(up + 1); uh[4] = v.x; uh[5] = v.y; uh[6] = v.z; uh[7] = v.w;
        v = __ldg(up + 2); uh[8] = v.x; uh[9] = v.y; uh[10] = v.z; uh[11] = v.w;
        v = __ldg(up + 3); uh[12] = v.x; uh[13] = v.y; uh[14] = v.z; uh[15] = v.w;
    }

    float blog = 0.0f;                     // routing logit b[b, c=lane, r]
    const bool hi4 = (lane & 16) != 0;
    const bool hi3 = (lane & 8) != 0;
    const bool hi2 = (lane & 4) != 0;
    const bool hi1 = (lane & 2) != 0;

#pragma unroll 1
    for (int it = 0; it < 3; ++it) {
        // coupling coefficient for this lane's c
        float cc;
        if (it == 0) {
            cc = 1.0f / 32.0f;             // softmax of zeros is exactly uniform
        } else {
            float m = blog;
#pragma unroll
            for (int s = 16; s > 0; s >>= 1)
                m = fmaxf(m, __shfl_xor_sync(FULL, m, s));
            float e = __expf(blog - m);
            float Z = e;
#pragma unroll
            for (int s = 16; s > 0; s >>= 1)
                Z += __shfl_xor_sync(FULL, Z, s);
            cc = e / Z;
        }

        // s[o] = sum_c cc*uh[c][o] via reduce-scatter (16 shfl); final o = lane>>1.
        float q[16];
#pragma unroll
        for (int o = 0; o < 16; ++o) q[o] = cc * uh[o];
        // level 16: keep 8 (upper-owned block if hi4)
#pragma unroll
        for (int i = 0; i < 8; ++i) {
            float snd = hi4 ? q[i] : q[i + 8];
            float kp  = hi4 ? q[i + 8] : q[i];
            q[i] = kp + __shfl_xor_sync(FULL, snd, 16);
        }
        // level 8
#pragma unroll
        for (int i = 0; i < 4; ++i) {
            float snd = hi3 ? q[i] : q[i + 4];
            float kp  = hi3 ? q[i + 4] : q[i];
            q[i] = kp + __shfl_xor_sync(FULL, snd, 8);
        }
        // level 4
#pragma unroll
        for (int i = 0; i < 2; ++i) {
            float snd = hi2 ? q[i] : q[i + 2];
            float kp  = hi2 ? q[i + 2] : q[i];
            q[i] = kp + __shfl_xor_sync(FULL, snd, 4);
        }
        // level 2
        float sp;
        {
            float snd = hi1 ? q[0] : q[1];
            float kp  = hi1 ? q[1] : q[0];
            sp = kp + __shfl_xor_sync(FULL, snd, 2);
        }
        // level 1: full sum; lanes l and l^1 now hold identical s[lane>>1]
        const float sv = sp + __shfl_xor_sync(FULL, sp, 1);

        // n2 = sum_o s[o]^2: xor over bits 4..1 hits each o exactly once
        float n2 = sv * sv;
        n2 += __shfl_xor_sync(FULL, n2, 16);
        n2 += __shfl_xor_sync(FULL, n2, 8);
        n2 += __shfl_xor_sync(FULL, n2, 4);
        n2 += __shfl_xor_sync(FULL, n2, 2);

        const float nrm = sqrtf(n2);
        const float vo  = (n2 / (1.0f + n2)) * (sv / nrm);

        if (it < 2) {
            // b[c] += sum_o uh[c][o]*v[o]  (v[o] lives at lane 2*o)
            float acc = 0.0f;
#pragma unroll
            for (int o2 = 0; o2 < 16; ++o2)
                acc = fmaf(uh[o2], __shfl_sync(FULL, vo, 2 * o2), acc);
            blog += acc;
        } else if ((lane & 1) == 0) {
            out[((size_t)b * R_ + r) * OUT_ + (lane >> 1)] = vo;
        }
    }
}

extern "C" void kernel_launch(void* const* d_in, const int* in_sizes, int n_in,
                              void* d_out, int out_size) {
    (void)n_in; (void)out_size;
    const float* a = (const float*)d_in[0];
    const float* b = (const float*)d_in[1];
    const float* X = a;
    const float* W = b;
    if (in_sizes[0] != B_ * IN_) { X = b; W = a; }

    cudaFuncSetAttribute(caps_gemm_kernel,
                         cudaFuncAttributeMaxDynamicSharedMemorySize, SMEM1_BYTES);
    caps_gemm_kernel<<<GEMM_CTAS, NT1, SMEM1_BYTES>>>(X, W);
    caps_route_kernel<<<(B_ * R_) / 8, 256>>>((float*)d_out);
}

// round 11
// speedup vs baseline: 1.4788x; 1.0298x over previous
#include <cuda_runtime.h>
#include <cuda_fp16.h>
#include <cstdint>
#include <cstddef>

// CapsuleLayer, two-kernel version.
//  K1: u_hat = x @ W  (fp16x3, mma.sync m16n8k16, SMEM-staged W, persistent CTAs,
//      256 thr / 2 CTAs per SM, 4 accumulator chains) -> g_uhat (b, r, c, o)
//  K2: dynamic routing, HALF-warp per (b,r): lanes 0-15 pair A, 16-31 pair B.
// B=64, C=32, R=1152, IN=128, OUT=16, ITERS=3.

#define B_      64
#define C_      32
#define R_      1152
#define IN_     128
#define OUT_    16
#define ROWB    80                         // W smem row: 32B hi + 32B lo + 16B pad
#define WTILE_B (IN_ * ROWB)               // one r tile (hi+lo): 10240 B
#define SMEM1_BYTES (2 * 2 * WTILE_B)      // 2 bufs x 2 r-tiles = 40960
#define GEMM_CTAS   288                    // persistent; 8 tasks each (288*8 = 2304)
#define NT1   256
#define BSTR  ((size_t)R_ * C_ * OUT_)     // b-stride in g_uhat = 589824

__device__ float g_uhat[(size_t)B_ * R_ * C_ * OUT_];   // 151 MB scratch

__device__ __forceinline__ unsigned h2bits(half2 h) {
    return *reinterpret_cast<unsigned*>(&h);
}
// v = hi + lo with hi,lo fp16 (packed pairs); ~22 effective bits
__device__ __forceinline__ void split2(float vx, float vy, unsigned& h, unsigned& l) {
    half2 hh = __floats2half2_rn(vx, vy);
    float2 hf = __half22float2(hh);
    half2 ll = __floats2half2_rn(vx - hf.x, vy - hf.y);
    h = h2bits(hh);
    l = h2bits(ll);
}

__device__ __forceinline__ void mma16(float& d0, float& d1, float& d2, float& d3,
                                      unsigned a0, unsigned a1, unsigned a2, unsigned a3,
                                      unsigned b0, unsigned b1) {
    asm volatile(
        "mma.sync.aligned.m16n8k16.row.col.f32.f16.f16.f32 "
        "{%0,%1,%2,%3}, {%4,%5,%6,%7}, {%8,%9}, {%0,%1,%2,%3};"
        : "+f"(d0), "+f"(d1), "+f"(d2), "+f"(d3)
        : "r"(a0), "r"(a1), "r"(a2), "r"(a3), "r"(b0), "r"(b1));
}

__device__ __forceinline__ void ldsm4t(unsigned& r0, unsigned& r1, unsigned& r2, unsigned& r3,
                                       unsigned addr) {
    asm volatile("ldmatrix.sync.aligned.m8n8.x4.trans.shared.b16 {%0,%1,%2,%3}, [%4];"
                 : "=r"(r0), "=r"(r1), "=r"(r2), "=r"(r3) : "r"(addr));
}

// ===================== Kernel 1: GEMM -> g_uhat =====================
// Task t (0..2303): c = t/72, rb = t%72 -> r block rb*16..rb*16+15.
// CTA does tasks bid*8 .. bid*8+7; 64 stages of 2 r-tiles (r = rb*16 + 2*(s&7) + g).
// Warps: p = warp&3 -> b-tile of 16 (2 mma n-tiles); g = warp>>2 (0/1) -> tile of stage.
// 4 accumulator chains: (n-tile 0/1) x (even/odd kc) to cover HMMA RAW latency.

extern "C" __global__ void __launch_bounds__(NT1, 2)
caps_gemm_kernel(const float* __restrict__ X,      // (B, IN)
                 const float* __restrict__ W)      // (C, R, IN, OUT)
{
    extern __shared__ char wbuf[];                  // 2 bufs x 2 tiles x WTILE_B

    const int bid   = blockIdx.x;
    const int tid   = threadIdx.x;
    const int warp  = tid >> 5;    // 0..7
    const int lane  = tid & 31;
    const int group = lane >> 2;   // 0..7
    const int tig   = lane & 3;    // 0..3
    const int p = warp & 3;
    const int g = warp >> 2;       // 0/1

    // x fragments (fp16 hi/lo), two n-tiles: b = 16p+group / 16p+8+group. Loaded ONCE.
    unsigned xh0[16], xl0[16], xh1[16], xl1[16];
    {
        const float2* xr0 = reinterpret_cast<const float2*>(X) + (size_t)(16 * p + group) * (IN_ / 2);
        const float2* xr1 = reinterpret_cast<const float2*>(X) + (size_t)(16 * p + 8 + group) * (IN_ / 2);
#pragma unroll
        for (int kc = 0; kc < 8; ++kc) {
            float2 v;
            v = __ldg(xr0 + 8 * kc + tig);
            split2(v.x, v.y, xh0[2 * kc], xl0[2 * kc]);
            v = __ldg(xr0 + 8 * kc + tig + 4);
            split2(v.x, v.y, xh0[2 * kc + 1], xl0[2 * kc + 1]);
            v = __ldg(xr1 + 8 * kc + tig);
            split2(v.x, v.y, xh1[2 * kc], xl1[2 * kc]);
            v = __ldg(xr1 + 8 * kc + tig + 4);
            split2(v.x, v.y, xh1[2 * kc + 1], xl1[2 * kc + 1]);
        }
    }

    // Staging role: thread t handles row i = t>>1, float4 pair at o4 = (t&1)*8, +4.
    const int st_i  = tid >> 1;            // 0..127
    const int st_h  = tid & 1;             // 0/1
    const int st_off = st_i * OUT_ + st_h * 8;       // float offset in tile

    const int lm_i = (lane & 7) + ((lane >> 4) << 3);
    const int lm_byte = lm_i * ROWB + ((lane & 8) ? 16 : 0);
    const unsigned wbuf_s = (unsigned)__cvta_generic_to_shared(wbuf);

    // stage -> W base of its 2 r tiles
    auto stage_base = [&](int s) -> const float* {
        int task = bid * 8 + (s >> 3);
        int c  = task / 72;
        int rb = task - c * 72;
        return W + ((size_t)c * R_ + rb * 16 + (s & 7) * 2) * (IN_ * OUT_);
    };

    // prefetch stage 0: 2 float4 per tile, 2 tiles
    const float* Ws = stage_base(0);
    float4 vA0 = __ldg(reinterpret_cast<const float4*>(Ws + st_off));
    float4 vA1 = __ldg(reinterpret_cast<const float4*>(Ws + st_off + 4));
    float4 vB0 = __ldg(reinterpret_cast<const float4*>(Ws + 2048 + st_off));
    float4 vB1 = __ldg(reinterpret_cast<const float4*>(Ws + 2048 + st_off + 4));

#pragma unroll 1
    for (int s = 0; s < 64; ++s) {
        const int buf = s & 1;
        // ---- split + store the 2 staged r tiles ----
        {
            const int b0 = st_i * ROWB + (st_h * 8) * 2;         // hi at +0, lo at +32
            char* baseA = wbuf + (size_t)(buf * 2 + 0) * WTILE_B + b0;
            char* baseB = wbuf + (size_t)(buf * 2 + 1) * WTILE_B + b0;
            unsigned h01, l01, h23, l23;
            split2(vA0.x, vA0.y, h01, l01);
            split2(vA0.z, vA0.w, h23, l23);
            *reinterpret_cast<uint2*>(baseA)      = make_uint2(h01, h23);
            *reinterpret_cast<uint2*>(baseA + 32) = make_uint2(l01, l23);
            split2(vA1.x, vA1.y, h01, l01);
            split2(vA1.z, vA1.w, h23, l23);
            *reinterpret_cast<uint2*>(baseA + 8)      = make_uint2(h01, h23);
            *reinterpret_cast<uint2*>(baseA + 8 + 32) = make_uint2(l01, l23);
            split2(vB0.x, vB0.y, h01, l01);
            split2(vB0.z, vB0.w, h23, l23);
            *reinterpret_cast<uint2*>(baseB)      = make_uint2(h01, h23);
            *reinterpret_cast<uint2*>(baseB + 32) = make_uint2(l01, l23);
            split2(vB1.x, vB1.y, h01, l01);
            split2(vB1.z, vB1.w, h23, l23);
            *reinterpret_cast<uint2*>(baseB + 8)      = make_uint2(h01, h23);
            *reinterpret_cast<uint2*>(baseB + 8 + 32) = make_uint2(l01, l23);
        }
        // ---- prefetch next stage ----
        if (s < 63) {
            const float* Wn = stage_base(s + 1);
            vA0 = __ldg(reinterpret_cast<const float4*>(Wn + st_off));
            vA1 = __ldg(reinterpret_cast<const float4*>(Wn + st_off + 4));
            vB0 = __ldg(reinterpret_cast<const float4*>(Wn + 2048 + st_off));
            vB1 = __ldg(reinterpret_cast<const float4*>(Wn + 2048 + st_off + 4));
        }
        __syncthreads();

        // ---- MMA on tile g of this stage; 4 chains (ntile x even/odd kc) ----
        const unsigned hbase = wbuf_s + (unsigned)(buf * 2 + g) * WTILE_B + lm_byte;

        float d0 = 0.f, d1 = 0.f, d2 = 0.f, d3 = 0.f;   // ntile0, even kc
        float e0 = 0.f, e1 = 0.f, e2 = 0.f, e3 = 0.f;   // ntile1, even kc
        float f0 = 0.f, f1 = 0.f, f2 = 0.f, f3 = 0.f;   // ntile0, odd kc
        float h0 = 0.f, h1 = 0.f, h2 = 0.f, h3 = 0.f;   // ntile1, odd kc
#pragma unroll
        for (int kc = 0; kc < 8; kc += 2) {
            unsigned ah0, ah1, ah2, ah3, al0, al1, al2, al3;   // even kc frags
            unsigned bh0, bh1, bh2, bh3, bl0, bl1, bl2, bl3;   // odd kc frags
            const unsigned ka = hbase + (unsigned)(16 * kc) * ROWB;
            ldsm4t(ah0, ah1, ah2, ah3, ka);
            ldsm4t(al0, al1, al2, al3, ka + 32);
            ldsm4t(bh0, bh1, bh2, bh3, ka + 16 * ROWB);
            ldsm4t(bl0, bl1, bl2, bl3, ka + 16 * ROWB + 32);
            const int k0 = 2 * kc, k1 = 2 * kc + 2;
            // interleave 4 independent chains: same-chain spacing = 4 MMAs (32 cyc)
            mma16(d0, d1, d2, d3, ah0, ah1, ah2, ah3, xh0[k0], xh0[k0 + 1]);
            mma16(e0, e1, e2, e3, ah0, ah1, ah2, ah3, xh1[k0], xh1[k0 + 1]);
            mma16(f0, f1, f2, f3, bh0, bh1, bh2, bh3, xh0[k1], xh0[k1 + 1]);
            mma16(h0, h1, h2, h3, bh0, bh1, bh2, bh3, xh1[k1], xh1[k1 + 1]);
            mma16(d0, d1, d2, d3, al0, al1, al2, al3, xh0[k0], xh0[k0 + 1]);
            mma16(e0, e1, e2, e3, al0, al1, al2, al3, xh1[k0], xh1[k0 + 1]);
            mma16(f0, f1, f2, f3, bl0, bl1, bl2, bl3, xh0[k1], xh0[k1 + 1]);
            mma16(h0, h1, h2, h3, bl0, bl1, bl2, bl3, xh1[k1], xh1[k1 + 1]);
            mma16(d0, d1, d2, d3, ah0, ah1, ah2, ah3, xl0[k0], xl0[k0 + 1]);
            mma16(e0, e1, e2, e3, ah0, ah1, ah2, ah3, xl1[k0], xl1[k0 + 1]);
            mma16(f0, f1, f2, f3, bh0, bh1, bh2, bh3, xl0[k1], xl0[k1 + 1]);
            mma16(h0, h1, h2, h3, bh0, bh1, bh2, bh3, xl1[k1], xl1[k1 + 1]);
        }
        d0 += f0; d1 += f1; d2 += f2; d3 += f3;
        e0 += h0; e1 += h1; e2 += h2; e3 += h3;

        // ---- store D frags to g_uhat (b, r, c, o) ----
        {
            int task = bid * 8 + (s >> 3);
            int c  = task / 72;
            int rb = task - c * 72;
            int r  = rb * 16 + (s & 7) * 2 + g;
            const size_t rc = ((size_t)r * C_ + c) * OUT_;
            const int b0 = 16 * p + 2 * tig;
            float* u0 = g_uhat + (size_t)b0 * BSTR + rc + group;
            u0[0]        = d0;
            u0[BSTR]     = d1;
            u0[8]        = d2;
            u0[BSTR + 8] = d3;
            float* u1 = u0 + 8 * BSTR;
            u1[0]        = e0;
            u1[BSTR]     = e1;
            u1[8]        = e2;
            u1[BSTR + 8] = e3;
        }
        __syncthreads();   // wbuf[buf] fully consumed before refill at s+2
    }
}

// ===================== Kernel 2: dynamic routing =====================
// HALF-warp per (b,r): lanes 0-15 pair A, 16-31 pair B. lane = c (two c's per
// lane: l16 and l16+16). Every shfl/fma serves two pairs.

extern "C" __global__ void __launch_bounds__(256)
caps_route_kernel(float* __restrict__ out)          // (B, R, OUT)
{
    const unsigned FULL = 0xffffffffu;
    const int lane = threadIdx.x & 31;
    const int l16  = lane & 15;
    const int hb   = lane & 16;            // half-base bit for in-half broadcasts
    const int pair = (blockIdx.x * 8 + (threadIdx.x >> 5)) * 2 + (lane >> 4);
    const int b = pair / R_;
    const int r = pair - b * R_;

    // uh0: u_hat[b,r, c=l16, :],  uh1: u_hat[b,r, c=l16+16, :]
    float uh0[16], uh1[16];
    {
        const float4* up = reinterpret_cast<const float4*>(
            g_uhat + ((size_t)b * R_ + r) * (C_ * OUT_) + l16 * OUT_);
        float4 v;
        v = __ldg(up + 0);  uh0[0] = v.x;  uh0[1] = v.y;  uh0[2] = v.z;  uh0[3] = v.w;
        v = __ldg(up + 1);  uh0[4] = v.x;  uh0[5] = v.y;  uh0[6] = v.z;  uh0[7] = v.w;
        v = __ldg(up + 2);  uh0[8] = v.x;  uh0[9] = v.y;  uh0[10] = v.z; uh0[11] = v.w;
        v = __ldg(up + 3);  uh0[12] = v.x; uh0[13] = v.y; uh0[14] = v.z; uh0[15] = v.w;
        v = __ldg(up + 64); uh1[0] = v.x;  uh1[1] = v.y;  uh1[2] = v.z;  uh1[3] = v.w;
        v = __ldg(up + 65); uh1[4] = v.x;  uh1[5] = v.y;  uh1[6] = v.z;  uh1[7] = v.w;
        v = __ldg(up + 66); uh1[8] = v.x;  uh1[9] = v.y;  uh1[10] = v.z; uh1[11] = v.w;
        v = __ldg(up + 67); uh1[12] = v.x; uh1[13] = v.y; uh1[14] = v.z; uh1[15] = v.w;
    }

    float blog0 = 0.0f, blog1 = 0.0f;      // logits for c=l16, c=l16+16
    const bool h3 = (l16 & 8) != 0;
    const bool h2 = (l16 & 4) != 0;
    const bool h1 = (l16 & 2) != 0;
    const bool h0 = (l16 & 1) != 0;

#pragma unroll 1
    for (int it = 0; it < 3; ++it) {
        // coupling coefficients (softmax over the 32 c's of this pair)
        float cc0, cc1;
        if (it == 0) {
            cc0 = cc1 = 1.0f / 32.0f;      // softmax of zeros is exactly uniform
        } else {
            float m = fmaxf(blog0, blog1);
#pragma unroll
            for (int s = 8; s > 0; s >>= 1)
                m = fmaxf(m, __shfl_xor_sync(FULL, m, s));
            float e0 = __expf(blog0 - m);
            float e1 = __expf(blog1 - m);
            float Z = e0 + e1;
#pragma unroll
            for (int s = 8; s > 0; s >>= 1)
                Z += __shfl_xor_sync(FULL, Z, s);
            cc0 = e0 / Z;
            cc1 = e1 / Z;
        }

        // s[o] = sum_c cc*uh  via 15-shfl reduce-scatter over the 16-lane half;
        // lane ends holding s[o = l16].
        float q[16];
#pragma unroll
        for (int o = 0; o < 16; ++o)
            q[o] = fmaf(cc1, uh1[o], cc0 * uh0[o]);
#pragma unroll
        for (int i = 0; i < 8; ++i) {      // level 8: o bit3 := lane bit3
            float snd = h3 ? q[i] : q[i + 8];
            float kp  = h3 ? q[i + 8] : q[i];
            q[i] = kp + __shfl_xor_sync(FULL, snd, 8);
        }
#pragma unroll
        for (int i = 0; i < 4; ++i) {      // level 4
            float snd = h2 ? q[i] : q[i + 2 + 2];
            float kp  = h2 ? q[i + 4] : q[i];
            q[i] = kp + __shfl_xor_sync(FULL, snd, 4);
        }
#pragma unroll
        for (int i = 0; i < 2; ++i) {      // level 2
            float snd = h1 ? q[i] : q[i + 2];
            float kp  = h1 ? q[i + 2] : q[i];
            q[i] = kp + __shfl_xor_sync(FULL, snd, 2);
        }
        float sv;
        {                                   // level 1
            float snd = h0 ? q[0] : q[1];
            float kp  = h0 ? q[1] : q[0];
            sv = kp + __shfl_xor_sync(FULL, snd, 1);
        }

        // n2 = sum_o s[o]^2 over the half
        float n2 = sv * sv;
        n2 += __shfl_xor_sync(FULL, n2, 8);
        n2 += __shfl_xor_sync(FULL, n2, 4);
        n2 += __shfl_xor_sync(FULL, n2, 2);
        n2 += __shfl_xor_sync(FULL, n2, 1);

        const float nrm = sqrtf(n2);
        const float vo  = (n2 / (1.0f + n2)) * (sv / nrm);

        if (it < 2) {
            // blog[c] += sum_o uh[c][o] * v[o]; v[o] lives at lane hb|o
            float a0 = 0.0f, a1 = 0.0f;
#pragma unroll
            for (int o2 = 0; o2 < 16; ++o2) {
                float vv = __shfl_sync(FULL, vo, hb | o2);
                a0 = fmaf(uh0[o2], vv, a0);
                a1 = fmaf(uh1[o2], vv, a1);
            }
            blog0 += a0;
            blog1 += a1;
        } else {
            out[((size_t)b * R_ + r) * OUT_ + l16] = vo;
        }
    }
}

extern "C" void kernel_launch(void* const* d_in, const int* in_sizes, int n_in,
                              void* d_out, int out_size) {
    (void)n_in; (void)out_size;
    const float* a = (const float*)d_in[0];
    const float* b = (const float*)d_in[1];
    const float* X = a;
    const float* W = b;
    if (in_sizes[0] != B_ * IN_) { X = b; W = a; }

    cudaFuncSetAttribute(caps_gemm_kernel,
                         cudaFuncAttributeMaxDynamicSharedMemorySize, SMEM1_BYTES);
    caps_gemm_kernel<<<GEMM_CTAS, NT1, SMEM1_BYTES>>>(X, W);
    caps_route_kernel<<<(B_ * R_) / 16, 256>>>((float*)d_out);
}